// round 5
// baseline (speedup 1.0000x reference)
#include <cuda_runtime.h>
#include <cuda_bf16.h>

#define T_TOK 4096
#define DMODEL 1024
#define NEXP 8
#define FFN 2048
#define TOPK 2
#define NPAIR (T_TOK * TOPK)

// ---------------- device scratch ----------------
__device__ int   g_cnt[NEXP];
__device__ int   g_off[NEXP + 1];
__device__ int   g_fill[NEXP];
__device__ int   g_pair_tok[NPAIR];
__device__ float g_pair_gate[NPAIR];
__device__ int   g_top_e[NPAIR];
__device__ float g_top_w[NPAIR];

__device__ __align__(16) __nv_bfloat16 g_xs_hi[(size_t)T_TOK * DMODEL];
__device__ __align__(16) __nv_bfloat16 g_xs_lo[(size_t)T_TOK * DMODEL];
__device__ __align__(16) __nv_bfloat16 g_w1_hi[(size_t)NEXP * FFN * DMODEL];
__device__ __align__(16) __nv_bfloat16 g_w1_lo[(size_t)NEXP * FFN * DMODEL];
__device__ __align__(16) __nv_bfloat16 g_v1_hi[(size_t)NEXP * FFN * DMODEL];
__device__ __align__(16) __nv_bfloat16 g_v1_lo[(size_t)NEXP * FFN * DMODEL];
__device__ __align__(16) __nv_bfloat16 g_w2t_hi[(size_t)NEXP * DMODEL * FFN];
__device__ __align__(16) __nv_bfloat16 g_w2t_lo[(size_t)NEXP * DMODEL * FFN];
__device__ __align__(16) __nv_bfloat16 g_h_hi[(size_t)NPAIR * FFN];
__device__ __align__(16) __nv_bfloat16 g_h_lo[(size_t)NPAIR * FFN];

// ---------------- helpers ----------------
__device__ __forceinline__ unsigned smem_u32(const void* p) {
    unsigned a;
    asm("{ .reg .u64 t; cvta.to.shared.u64 t, %1; cvt.u32.u64 %0, t; }"
        : "=r"(a) : "l"(p));
    return a;
}
// swizzled byte offset in a [rows][32 bf16] tile (64B rows); c must be < 64
__device__ __forceinline__ unsigned swz(int row, int c) {
    return (unsigned)(row * 64 + (c ^ ((row & 6) << 3)));
}
__device__ __forceinline__ void ldm4(unsigned* r, unsigned addr) {
    asm volatile("ldmatrix.sync.aligned.m8n8.x4.shared.b16 {%0,%1,%2,%3}, [%4];"
                 : "=r"(r[0]), "=r"(r[1]), "=r"(r[2]), "=r"(r[3]) : "r"(addr));
}
__device__ __forceinline__ void mma16816(float* c, const unsigned* a, const unsigned* b) {
    asm volatile(
        "mma.sync.aligned.m16n8k16.row.col.f32.bf16.bf16.f32 "
        "{%0,%1,%2,%3}, {%4,%5,%6,%7}, {%8,%9}, {%0,%1,%2,%3};"
        : "+f"(c[0]), "+f"(c[1]), "+f"(c[2]), "+f"(c[3])
        : "r"(a[0]), "r"(a[1]), "r"(a[2]), "r"(a[3]), "r"(b[0]), "r"(b[1]));
}
__device__ __forceinline__ void cpa16(unsigned d, const void* s, unsigned bytes) {
    asm volatile("cp.async.ca.shared.global [%0], [%1], 16, %2;"
                 :: "r"(d), "l"(s), "r"(bytes) : "memory");
}
#define CP_COMMIT() asm volatile("cp.async.commit_group;" ::: "memory")
#define CP_WAIT2()  asm volatile("cp.async.wait_group 2;" ::: "memory")

// pack (a->lo, b->hi) bf16x2, return residuals
__device__ __forceinline__ unsigned bf2_hi(float a, float b, float& ra, float& rb) {
    unsigned h;
    asm("cvt.rn.bf16x2.f32 %0, %1, %2;" : "=r"(h) : "f"(b), "f"(a));
    ra = a - __uint_as_float(h << 16);
    rb = b - __uint_as_float(h & 0xffff0000u);
    return h;
}
__device__ __forceinline__ unsigned bf2(float a, float b) {
    unsigned h;
    asm("cvt.rn.bf16x2.f32 %0, %1, %2;" : "=r"(h) : "f"(b), "f"(a));
    return h;
}

// ---------------- init ----------------
__global__ void init_kernel(float* __restrict__ out, int n) {
    int i = blockIdx.x * blockDim.x + threadIdx.x;
    if (i < n) out[i] = 0.0f;
    if (i < NEXP) { g_cnt[i] = 0; g_fill[i] = 0; }
}

// ---------------- router ----------------
__global__ void router_kernel(const float* __restrict__ x, const float* __restrict__ rw) {
    const int t   = blockIdx.x;
    const int tid = threadIdx.x;
    const float4 xr = reinterpret_cast<const float4*>(x + (size_t)t * DMODEL)[tid];
    float part[NEXP];
#pragma unroll
    for (int e = 0; e < NEXP; ++e) {
        const float4 w = reinterpret_cast<const float4*>(rw + (size_t)e * DMODEL)[tid];
        part[e] = xr.x * w.x + xr.y * w.y + xr.z * w.z + xr.w * w.w;
    }
#pragma unroll
    for (int e = 0; e < NEXP; ++e)
#pragma unroll
        for (int o = 16; o > 0; o >>= 1)
            part[e] += __shfl_down_sync(0xffffffffu, part[e], o);
    __shared__ float sm[NEXP][8];
    const int warp = tid >> 5, lane = tid & 31;
    if (lane == 0)
#pragma unroll
        for (int e = 0; e < NEXP; ++e) sm[e][warp] = part[e];
    __syncthreads();
    if (tid == 0) {
        float lg[NEXP]; float mx = -1e30f;
#pragma unroll
        for (int e = 0; e < NEXP; ++e) {
            float s = 0.f;
#pragma unroll
            for (int w = 0; w < 8; ++w) s += sm[e][w];
            lg[e] = s; mx = fmaxf(mx, s);
        }
        float den = 0.f;
#pragma unroll
        for (int e = 0; e < NEXP; ++e) { lg[e] = expf(lg[e] - mx); den += lg[e]; }
#pragma unroll
        for (int e = 0; e < NEXP; ++e) lg[e] /= den;
        int e0 = 0; float v0 = lg[0];
#pragma unroll
        for (int e = 1; e < NEXP; ++e) if (lg[e] > v0) { v0 = lg[e]; e0 = e; }
        int e1 = -1; float v1 = -1.f;
#pragma unroll
        for (int e = 0; e < NEXP; ++e)
            if (e != e0 && lg[e] > v1) { v1 = lg[e]; e1 = e; }
        const float nrm = v0 + v1;
        g_top_e[t * 2 + 0] = e0; g_top_w[t * 2 + 0] = v0 / nrm;
        g_top_e[t * 2 + 1] = e1; g_top_w[t * 2 + 1] = v1 / nrm;
        atomicAdd(&g_cnt[e0], 1);
        atomicAdd(&g_cnt[e1], 1);
    }
}

__global__ void offsets_kernel() {
    g_off[0] = 0;
    for (int e = 0; e < NEXP; ++e) g_off[e + 1] = g_off[e] + g_cnt[e];
}

__global__ void scatter_kernel() {
    int t = blockIdx.x * blockDim.x + threadIdx.x;
    if (t >= T_TOK) return;
#pragma unroll
    for (int k = 0; k < TOPK; ++k) {
        int e = g_top_e[t * TOPK + k];
        int pos = g_off[e] + atomicAdd(&g_fill[e], 1);
        g_pair_tok[pos]  = t;
        g_pair_gate[pos] = g_top_w[t * TOPK + k];
    }
}

// ---------------- generic fp32 -> bf16 hi/lo split ----------------
__global__ void split_kernel(const float* __restrict__ s, __nv_bfloat16* __restrict__ hi,
                             __nv_bfloat16* __restrict__ lo, int n4) {
    int i = blockIdx.x * blockDim.x + threadIdx.x;
    if (i >= n4) return;
    float4 v = reinterpret_cast<const float4*>(s)[i];
    __nv_bfloat16 h0 = __float2bfloat16(v.x), h1 = __float2bfloat16(v.y);
    __nv_bfloat16 h2 = __float2bfloat16(v.z), h3 = __float2bfloat16(v.w);
    __nv_bfloat162* ph = reinterpret_cast<__nv_bfloat162*>(hi) + i * 2;
    ph[0] = __nv_bfloat162(h0, h1);
    ph[1] = __nv_bfloat162(h2, h3);
    __nv_bfloat162* pl = reinterpret_cast<__nv_bfloat162*>(lo) + i * 2;
    pl[0] = __nv_bfloat162(__float2bfloat16(v.x - __bfloat162float(h0)),
                           __float2bfloat16(v.y - __bfloat162float(h1)));
    pl[1] = __nv_bfloat162(__float2bfloat16(v.z - __bfloat162float(h2)),
                           __float2bfloat16(v.w - __bfloat162float(h3)));
}

// ---------------- w2 transpose + split: w2t[e][d][f] ----------------
__global__ void split_w2t_kernel(const float* __restrict__ w2) {
    __shared__ float t[32][33];
    const int e = blockIdx.z;
    const int f0 = blockIdx.x * 32, d0 = blockIdx.y * 32;
    const int tx = threadIdx.x, ty = threadIdx.y;   // 32 x 8
#pragma unroll
    for (int j = 0; j < 4; ++j)
        t[ty + j * 8][tx] = w2[((size_t)e * FFN + f0 + ty + j * 8) * DMODEL + d0 + tx];
    __syncthreads();
#pragma unroll
    for (int j = 0; j < 4; ++j) {
        const int dl = ty + j * 8;
        float v = t[tx][dl];
        __nv_bfloat16 hi = __float2bfloat16(v);
        size_t o = ((size_t)e * DMODEL + d0 + dl) * FFN + f0 + tx;
        g_w2t_hi[o] = hi;
        g_w2t_lo[o] = __float2bfloat16(v - __bfloat162float(hi));
    }
}

// ---------------- GEMM tile constants ----------------
#define STG_SZ 32768
#define OFF_AH 0
#define OFF_AL 8192
#define OFF_BH 16384
#define OFF_BL 24576

// ============ GEMM1 (fused): h = silu(x@w1^T) * (x@v1^T), bf16-split out =======
// Tile: 128 pairs x 64 F cols. B smem rows 0-63 = w1, 64-127 = v1.
// Warps 0-3 (mat=0) compute w1 product; warps 4-7 (mat=1) compute v1 product.
// Epilogue: v1 tile staged via smem, w1 warps apply SwiGLU + split, write h.
__global__ void __launch_bounds__(256, 1) gemm1_kernel() {
    extern __shared__ char smem[];
    __shared__ int toks[128];
    const unsigned sb = smem_u32(smem);
    const int tid = threadIdx.x, lane = tid & 31, wid = tid >> 5;
    const int n0 = blockIdx.x * 64;
    const int e = blockIdx.y;
    const int off = g_off[e], cnt = g_cnt[e];

    const int mat = wid >> 2, wm = (wid >> 1) & 1, wn = wid & 1;
    unsigned aoffs[2][4], boffs[2][2];
#pragma unroll
    for (int ks = 0; ks < 2; ++ks) {
#pragma unroll
        for (int m = 0; m < 4; ++m) {
            int r = wm * 64 + m * 16 + ((lane >> 3) & 1) * 8 + (lane & 7);
            aoffs[ks][m] = swz(r, ((lane >> 4) << 4) + ks * 32);
        }
#pragma unroll
        for (int np = 0; np < 2; ++np) {
            int r = mat * 64 + wn * 32 + np * 16 + ((lane >> 4) << 3) + (lane & 7);
            boffs[ks][np] = swz(r, (((lane >> 3) & 1) << 4) + ks * 32);
        }
    }
    const int prow0 = tid >> 2;
    const int pc16 = (tid & 3) * 16;
    const int pc8  = (tid & 3) * 8;
    unsigned soffs[2];
    soffs[0] = swz(prow0, pc16);
    soffs[1] = swz(prow0 + 64, pc16);
    const size_t wbase = ((size_t)e * FFN + n0 + prow0) * DMODEL + pc8;

    for (int mt = blockIdx.z; mt * 128 < cnt; mt += gridDim.z) {
        if (tid < 128) {
            int r = mt * 128 + tid;
            toks[tid] = (r < cnt) ? g_pair_tok[off + r] : -1;
        }
        __syncthreads();
        const int tok0 = toks[prow0], tok1 = toks[prow0 + 64];
        const size_t a0 = (size_t)(tok0 >= 0 ? tok0 : 0) * DMODEL + pc8;
        const size_t a1 = (size_t)(tok1 >= 0 ? tok1 : 0) * DMODEL + pc8;
        const unsigned p0 = tok0 >= 0 ? 16u : 0u, p1 = tok1 >= 0 ? 16u : 0u;

#define G1_ISSUE(C) {                                                             \
        const unsigned st = sb + ((C) % 3) * STG_SZ;                              \
        const int k0 = (C) * 32;                                                  \
        cpa16(st + OFF_AH + soffs[0], g_xs_hi + a0 + k0, p0);                     \
        cpa16(st + OFF_AL + soffs[0], g_xs_lo + a0 + k0, p0);                     \
        cpa16(st + OFF_AH + soffs[1], g_xs_hi + a1 + k0, p1);                     \
        cpa16(st + OFF_AL + soffs[1], g_xs_lo + a1 + k0, p1);                     \
        cpa16(st + OFF_BH + soffs[0], g_w1_hi + wbase + k0, 16u);                 \
        cpa16(st + OFF_BL + soffs[0], g_w1_lo + wbase + k0, 16u);                 \
        cpa16(st + OFF_BH + soffs[1], g_v1_hi + wbase + k0, 16u);                 \
        cpa16(st + OFF_BL + soffs[1], g_v1_lo + wbase + k0, 16u); }

        float acc[4][4][4];
#pragma unroll
        for (int m = 0; m < 4; ++m)
#pragma unroll
            for (int n = 0; n < 4; ++n)
#pragma unroll
                for (int q = 0; q < 4; ++q) acc[m][n][q] = 0.f;

        G1_ISSUE(0) CP_COMMIT();
        G1_ISSUE(1) CP_COMMIT();
        for (int c = 0; c < DMODEL / 32; ++c) {
            if (c + 2 < DMODEL / 32) G1_ISSUE(c + 2)
            CP_COMMIT();
            CP_WAIT2();
            __syncthreads();
            const unsigned so = (unsigned)(c % 3) * STG_SZ;
#pragma unroll
            for (int ks = 0; ks < 2; ++ks) {
                unsigned aH[4][4], aL[4][4], bH[2][4], bL[2][4];
#pragma unroll
                for (int m = 0; m < 4; ++m) {
                    ldm4(aH[m], sb + so + OFF_AH + aoffs[ks][m]);
                    ldm4(aL[m], sb + so + OFF_AL + aoffs[ks][m]);
                }
#pragma unroll
                for (int np = 0; np < 2; ++np) {
                    ldm4(bH[np], sb + so + OFF_BH + boffs[ks][np]);
                    ldm4(bL[np], sb + so + OFF_BL + boffs[ks][np]);
                }
#pragma unroll
                for (int np = 0; np < 2; ++np)
#pragma unroll
                    for (int hf = 0; hf < 2; ++hf)
#pragma unroll
                        for (int m = 0; m < 4; ++m)
                            mma16816(acc[m][np * 2 + hf], aH[m], &bH[np][hf * 2]);
#pragma unroll
                for (int np = 0; np < 2; ++np)
#pragma unroll
                    for (int hf = 0; hf < 2; ++hf)
#pragma unroll
                        for (int m = 0; m < 4; ++m)
                            mma16816(acc[m][np * 2 + hf], aH[m], &bL[np][hf * 2]);
#pragma unroll
                for (int np = 0; np < 2; ++np)
#pragma unroll
                    for (int hf = 0; hf < 2; ++hf)
#pragma unroll
                        for (int m = 0; m < 4; ++m)
                            mma16816(acc[m][np * 2 + hf], aL[m], &bH[np][hf * 2]);
            }
            __syncthreads();
        }
        // ---- epilogue: exchange v1 tile via smem, SwiGLU on w1 warps ----
        float (*exch)[68] = reinterpret_cast<float (*)[68]>(smem);
        if (mat == 1) {
#pragma unroll
            for (int m = 0; m < 4; ++m)
#pragma unroll
                for (int hf = 0; hf < 2; ++hf) {
                    const int row = wm * 64 + m * 16 + (lane >> 2) + hf * 8;
#pragma unroll
                    for (int n = 0; n < 4; ++n) {
                        const int col = wn * 32 + n * 8 + (lane & 3) * 2;
                        exch[row][col]     = acc[m][n][hf * 2];
                        exch[row][col + 1] = acc[m][n][hf * 2 + 1];
                    }
                }
        }
        __syncthreads();
        if (mat == 0) {
#pragma unroll
            for (int m = 0; m < 4; ++m)
#pragma unroll
                for (int hf = 0; hf < 2; ++hf) {
                    const int row = wm * 64 + m * 16 + (lane >> 2) + hf * 8;
                    const int rl = mt * 128 + row;
                    if (rl < cnt) {
                        const size_t rbase = (size_t)(off + rl) * FFN + n0;
#pragma unroll
                        for (int n = 0; n < 4; ++n) {
                            const int col = wn * 32 + n * 8 + (lane & 3) * 2;
                            const float g0 = acc[m][n][hf * 2];
                            const float g1 = acc[m][n][hf * 2 + 1];
                            const float l0 = exch[row][col];
                            const float l1 = exch[row][col + 1];
                            const float h0 = g0 / (1.f + __expf(-g0)) * l0;
                            const float h1 = g1 / (1.f + __expf(-g1)) * l1;
                            float ra, rb;
                            const unsigned hp = bf2_hi(h0, h1, ra, rb);
                            const unsigned lp = bf2(ra, rb);
                            *reinterpret_cast<unsigned*>(
                                reinterpret_cast<char*>(g_h_hi) + (rbase + col) * 2) = hp;
                            *reinterpret_cast<unsigned*>(
                                reinterpret_cast<char*>(g_h_lo) + (rbase + col) * 2) = lp;
                        }
                    }
                }
        }
        __syncthreads();
    }
}

// ============ GEMM2: out += gate * (h @ w2t^T) ============
__global__ void __launch_bounds__(256, 1) gemm2_kernel(float* __restrict__ out) {
    extern __shared__ char smem[];
    const unsigned sb = smem_u32(smem);
    const int tid = threadIdx.x, lane = tid & 31, wid = tid >> 5;
    const int n0 = blockIdx.x * 128;
    const int e = blockIdx.y;
    const int off = g_off[e], cnt = g_cnt[e];

    const int wm = wid & 1, wn = wid >> 1;
    unsigned aoffs[2][4], boffs[2][2];
#pragma unroll
    for (int ks = 0; ks < 2; ++ks) {
#pragma unroll
        for (int m = 0; m < 4; ++m) {
            int r = wm * 64 + m * 16 + ((lane >> 3) & 1) * 8 + (lane & 7);
            aoffs[ks][m] = swz(r, ((lane >> 4) << 4) + ks * 32);
        }
#pragma unroll
        for (int np = 0; np < 2; ++np) {
            int r = wn * 32 + np * 16 + ((lane >> 4) << 3) + (lane & 7);
            boffs[ks][np] = swz(r, (((lane >> 3) & 1) << 4) + ks * 32);
        }
    }
    const int prow0 = tid >> 2;
    const int pc16 = (tid & 3) * 16;
    const int pc8  = (tid & 3) * 8;
    unsigned soffs[2];
    soffs[0] = swz(prow0, pc16);
    soffs[1] = swz(prow0 + 64, pc16);
    const size_t b0 = ((size_t)e * DMODEL + n0 + prow0) * FFN + pc8;
    const size_t b1 = ((size_t)e * DMODEL + n0 + prow0 + 64) * FFN + pc8;

    for (int mt = blockIdx.z; mt * 128 < cnt; mt += gridDim.z) {
        const int rl0 = mt * 128 + prow0, rl1 = rl0 + 64;
        const size_t a0 = (size_t)(off + (rl0 < cnt ? rl0 : 0)) * FFN + pc8;
        const size_t a1 = (size_t)(off + (rl1 < cnt ? rl1 : 0)) * FFN + pc8;
        const unsigned p0 = rl0 < cnt ? 16u : 0u, p1 = rl1 < cnt ? 16u : 0u;

#define G2_ISSUE(C) {                                                             \
        const unsigned st = sb + ((C) % 3) * STG_SZ;                              \
        const int k0 = (C) * 32;                                                  \
        cpa16(st + OFF_AH + soffs[0], g_h_hi + a0 + k0, p0);                      \
        cpa16(st + OFF_AL + soffs[0], g_h_lo + a0 + k0, p0);                      \
        cpa16(st + OFF_AH + soffs[1], g_h_hi + a1 + k0, p1);                      \
        cpa16(st + OFF_AL + soffs[1], g_h_lo + a1 + k0, p1);                      \
        cpa16(st + OFF_BH + soffs[0], g_w2t_hi + b0 + k0, 16u);                   \
        cpa16(st + OFF_BL + soffs[0], g_w2t_lo + b0 + k0, 16u);                   \
        cpa16(st + OFF_BH + soffs[1], g_w2t_hi + b1 + k0, 16u);                   \
        cpa16(st + OFF_BL + soffs[1], g_w2t_lo + b1 + k0, 16u); }

        float acc[4][4][4];
#pragma unroll
        for (int m = 0; m < 4; ++m)
#pragma unroll
            for (int n = 0; n < 4; ++n)
#pragma unroll
                for (int q = 0; q < 4; ++q) acc[m][n][q] = 0.f;

        G2_ISSUE(0) CP_COMMIT();
        G2_ISSUE(1) CP_COMMIT();
        for (int c = 0; c < FFN / 32; ++c) {
            if (c + 2 < FFN / 32) G2_ISSUE(c + 2)
            CP_COMMIT();
            CP_WAIT2();
            __syncthreads();
            const unsigned so = (unsigned)(c % 3) * STG_SZ;
#pragma unroll
            for (int ks = 0; ks < 2; ++ks) {
                unsigned aH[4][4], aL[4][4], bH[2][4], bL[2][4];
#pragma unroll
                for (int m = 0; m < 4; ++m) {
                    ldm4(aH[m], sb + so + OFF_AH + aoffs[ks][m]);
                    ldm4(aL[m], sb + so + OFF_AL + aoffs[ks][m]);
                }
#pragma unroll
                for (int np = 0; np < 2; ++np) {
                    ldm4(bH[np], sb + so + OFF_BH + boffs[ks][np]);
                    ldm4(bL[np], sb + so + OFF_BL + boffs[ks][np]);
                }
#pragma unroll
                for (int np = 0; np < 2; ++np)
#pragma unroll
                    for (int hf = 0; hf < 2; ++hf)
#pragma unroll
                        for (int m = 0; m < 4; ++m)
                            mma16816(acc[m][np * 2 + hf], aH[m], &bH[np][hf * 2]);
#pragma unroll
                for (int np = 0; np < 2; ++np)
#pragma unroll
                    for (int hf = 0; hf < 2; ++hf)
#pragma unroll
                        for (int m = 0; m < 4; ++m)
                            mma16816(acc[m][np * 2 + hf], aH[m], &bL[np][hf * 2]);
#pragma unroll
                for (int np = 0; np < 2; ++np)
#pragma unroll
                    for (int hf = 0; hf < 2; ++hf)
#pragma unroll
                        for (int m = 0; m < 4; ++m)
                            mma16816(acc[m][np * 2 + hf], aL[m], &bH[np][hf * 2]);
            }
            __syncthreads();
        }
        // epilogue: gate-scaled atomic combine (2 adds per output elem total)
#pragma unroll
        for (int m = 0; m < 4; ++m)
#pragma unroll
            for (int hf = 0; hf < 2; ++hf) {
                const int rl = mt * 128 + wm * 64 + m * 16 + (lane >> 2) + hf * 8;
                if (rl < cnt) {
                    const int   tok = g_pair_tok[off + rl];
                    const float gt  = g_pair_gate[off + rl];
                    float* dst = out + (size_t)tok * DMODEL + n0 + wn * 32 + (lane & 3) * 2;
#pragma unroll
                    for (int n = 0; n < 4; ++n) {
                        atomicAdd(dst + n * 8 + 0, gt * acc[m][n][hf * 2]);
                        atomicAdd(dst + n * 8 + 1, gt * acc[m][n][hf * 2 + 1]);
                    }
                }
            }
    }
}

// ---------------- launch ----------------
extern "C" void kernel_launch(void* const* d_in, const int* in_sizes, int n_in,
                              void* d_out, int out_size) {
    const float* x  = (const float*)d_in[0];
    const float* w1 = (const float*)d_in[1];
    const float* v1 = (const float*)d_in[2];
    const float* w2 = (const float*)d_in[3];
    const float* rw = (const float*)d_in[4];
    float* out = (float*)d_out;

    cudaFuncSetAttribute(gemm1_kernel, cudaFuncAttributeMaxDynamicSharedMemorySize, 3 * STG_SZ);
    cudaFuncSetAttribute(gemm2_kernel, cudaFuncAttributeMaxDynamicSharedMemorySize, 3 * STG_SZ);

    init_kernel<<<(T_TOK * DMODEL + 255) / 256, 256>>>(out, T_TOK * DMODEL);
    router_kernel<<<T_TOK, 256>>>(x, rw);
    offsets_kernel<<<1, 1>>>();
    scatter_kernel<<<(T_TOK + 255) / 256, 256>>>();

    __nv_bfloat16 *xs_hi, *xs_lo, *w1_hi, *w1_lo, *v1_hi, *v1_lo;
    cudaGetSymbolAddress((void**)&xs_hi, g_xs_hi);
    cudaGetSymbolAddress((void**)&xs_lo, g_xs_lo);
    cudaGetSymbolAddress((void**)&w1_hi, g_w1_hi);
    cudaGetSymbolAddress((void**)&w1_lo, g_w1_lo);
    cudaGetSymbolAddress((void**)&v1_hi, g_v1_hi);
    cudaGetSymbolAddress((void**)&v1_lo, g_v1_lo);

    const int nx4 = T_TOK * DMODEL / 4;
    const int nw4 = NEXP * FFN * DMODEL / 4;
    split_kernel<<<(nx4 + 255) / 256, 256>>>(x, xs_hi, xs_lo, nx4);
    split_kernel<<<(nw4 + 255) / 256, 256>>>(w1, w1_hi, w1_lo, nw4);
    split_kernel<<<(nw4 + 255) / 256, 256>>>(v1, v1_hi, v1_lo, nw4);
    split_w2t_kernel<<<dim3(FFN / 32, DMODEL / 32, NEXP), dim3(32, 8)>>>(w2);

    gemm1_kernel<<<dim3(FFN / 64, NEXP, 4), 256, 3 * STG_SZ>>>();
    gemm2_kernel<<<dim3(DMODEL / 128, NEXP, 8), 256, 3 * STG_SZ>>>(out);
}